// round 6
// baseline (speedup 1.0000x reference)
#include <cuda_runtime.h>
#include <cuda_bf16.h>
#include <cstdint>

// BitLevelMapper: B=4194304 rows x 16 bits.
// bits:   [B,16] int32 {0,1}  (d_in[0])
// tables: [16, 32768] float32 {0,1} (d_in[1])
// out:    [B,16] float32
//
// R6: nibble-fused lookup tables. Lane group q handles bit rows
// i = base..base+3 (base = 12-4q); a fused entry indexed by the
// (base+3)-bit prefix of P packs all 4 flip bits as one nibble.
// Inner loop: 1 LDS + 1 extract + 1 XOR replaces 4 LDS + 4 extracts.
// Registers stay <=32 -> 8 CTAs/SM, 64 warps (R5's full occupancy kept).

#define NBITS    16
#define TSIZE    32768          // 2^15 entries per table row
// fused words per group: G0(base=12):4096, G1(base=8):256, G2(base=4):16, G3(base=0):1
#define NFWORDS  4369

__device__ uint32_t g_fused[NFWORDS];

// word offsets of the 4 fused groups (group g has base = 12-4g)
#define OFF_G0 0
#define OFF_G1 4096
#define OFF_G2 4352
#define OFF_G3 4368

// One thread per fused word: 8 entries x 4 table reads (L2-cached, tiny).
__global__ void pack_fused_kernel(const float* __restrict__ tables) {
    int w = blockIdx.x * blockDim.x + threadIdx.x;
    if (w >= NFWORDS) return;
    int base, lw;
    if      (w < OFF_G1) { base = 12; lw = w - OFF_G0; }
    else if (w < OFF_G2) { base = 8;  lw = w - OFF_G1; }
    else if (w < OFF_G3) { base = 4;  lw = w - OFF_G2; }
    else                 { base = 0;  lw = 0; }
    uint32_t word = 0;
    #pragma unroll 2
    for (int e = 0; e < 8; e++) {
        int a = lw * 8 + e;               // fused entry index (prefix bits of P)
        #pragma unroll
        for (int k = 0; k < 4; k++) {
            int i = base + k;
            int addr = a & ((1 << i) - 1); // context address for bit row i
            if (tables[(size_t)i * TSIZE + addr] != 0.0f)
                word |= 1u << (e * 4 + k);
        }
    }
    g_fused[w] = word;
}

#define MAP_BLOCKS  1216        // 152 SMs x 8 CTAs: one full resident wave
#define MAP_THREADS 256

__global__ void __launch_bounds__(MAP_THREADS, 8)
map_kernel(const int4* __restrict__ bits4, float4* __restrict__ out4, int nquads) {
    __shared__ uint32_t s_tab[NFWORDS];
    for (int t = threadIdx.x; t < NFWORDS; t += blockDim.x)
        s_tab[t] = g_fused[t];
    __syncthreads();

    const int stride = gridDim.x * blockDim.x;
    const int base_t = blockIdx.x * blockDim.x + threadIdx.x;
    const int q      = base_t & 3;          // quarter within row (lane-group pos)
    const int shift  = 15 - 4 * q;          // bit position of v.x in pattern P
    const int ibase  = shift - 3;           // lowest bit row this lane handles
    const unsigned mask = (1u << shift) - 1u;   // (base+3)-bit prefix mask
    const int offq   = (q == 0) ? OFF_G0 : (q == 1) ? OFF_G1
                                         : (q == 2) ? OFF_G2 : OFF_G3;

    const int nmain = nquads / stride;      // uniform across all threads

    for (int it = 0; it < nmain; it++) {
        int t = base_t + it * stride;
        int4 v = bits4[t];

        // partial 16-bit pattern: bit j (array order) sits at position 15-j
        unsigned P = ((unsigned)v.x << shift)       | ((unsigned)v.y << (shift - 1))
                   | ((unsigned)v.z << (shift - 2)) | ((unsigned)v.w << (shift - 3));
        // OR-reduce across the aligned 4-lane group -> full pattern in all 4 lanes
        P |= __shfl_xor_sync(0xffffffffu, P, 1);
        P |= __shfl_xor_sync(0xffffffffu, P, 2);

        unsigned addr  = P & mask;                       // prefix of context
        uint32_t wv    = s_tab[offq + (addr >> 3)];
        unsigned flips = (wv >> ((addr & 7u) << 2)) & 0xFu;   // nibble: bit k = flip(i=ibase+k)
        unsigned x4    = ((P >> ibase) ^ flips) & 0xFu;       // input ^ flip, 4 bits

        // o[m] is output column j=4q+m -> bit row i=shift-m -> bit (3-m) of x4
        float4 o;
        o.x = __uint_as_float((0u - ((x4 >> 3) & 1u)) & 0x3f800000u);
        o.y = __uint_as_float((0u - ((x4 >> 2) & 1u)) & 0x3f800000u);
        o.z = __uint_as_float((0u - ((x4 >> 1) & 1u)) & 0x3f800000u);
        o.w = __uint_as_float((0u - ( x4       & 1u)) & 0x3f800000u);
        out4[t] = o;
    }

    // tail: remaining quads (scalar per-row path, no shuffles; ~1.7% of work)
    for (int t = base_t + nmain * stride; t < nquads; t += stride) {
        int row = t >> 2, qq = t & 3;
        const int4* rp = bits4 + (size_t)row * 4;
        int4 r0 = rp[0], r1 = rp[1], r2 = rp[2], r3 = rp[3];
        int b[16] = { r0.x, r0.y, r0.z, r0.w, r1.x, r1.y, r1.z, r1.w,
                      r2.x, r2.y, r2.z, r2.w, r3.x, r3.y, r3.z, r3.w };
        unsigned P = 0;
        #pragma unroll
        for (int j = 0; j < 16; j++) P |= ((unsigned)b[j] & 1u) << (15 - j);
        int tsh   = 15 - 4 * qq;
        int tbase = tsh - 3;
        unsigned tmask = (1u << tsh) - 1u;
        int toff  = (qq == 0) ? OFF_G0 : (qq == 1) ? OFF_G1
                                       : (qq == 2) ? OFF_G2 : OFF_G3;
        unsigned addr  = P & tmask;
        uint32_t wv    = s_tab[toff + (addr >> 3)];
        unsigned flips = (wv >> ((addr & 7u) << 2)) & 0xFu;
        unsigned x4    = ((P >> tbase) ^ flips) & 0xFu;
        float4 o;
        o.x = __uint_as_float((0u - ((x4 >> 3) & 1u)) & 0x3f800000u);
        o.y = __uint_as_float((0u - ((x4 >> 2) & 1u)) & 0x3f800000u);
        o.z = __uint_as_float((0u - ((x4 >> 1) & 1u)) & 0x3f800000u);
        o.w = __uint_as_float((0u - ( x4       & 1u)) & 0x3f800000u);
        out4[t] = o;
    }
}

extern "C" void kernel_launch(void* const* d_in, const int* in_sizes, int n_in,
                              void* d_out, int out_size) {
    const int4*  bits4  = (const int4*)d_in[0];
    const float* tables = (const float*)d_in[1];
    float4*      out4   = (float4*)d_out;

    int nquads = in_sizes[0] / 4;      // 16777216

    pack_fused_kernel<<<(NFWORDS + 255) / 256, 256>>>(tables);
    map_kernel<<<MAP_BLOCKS, MAP_THREADS>>>(bits4, out4, nquads);
}